// round 7
// baseline (speedup 1.0000x reference)
#include <cuda_runtime.h>
#include <cuda_bf16.h>
#include <math.h>

#define NNODES 50000
#define FDIM   128
#define NPROTO 50
#define NCLS   10
#define EPSV   1e-4f
#define EMAX   640000

// ---------------- scratch (device globals; no allocation) ----------------
__device__ int    g_is64;                     // edge_index dtype flag
__device__ float  g_dinv[NNODES];             // deg^{-1/2}
__device__ int    g_degi[NNODES];             // edge-only in-degree
__device__ int    g_rowptr[NNODES + 1];
__device__ int    g_cursor[NNODES];
__device__ int    g_csrsrc[EMAX];
__device__ float  g_csrw[EMAX];
__device__ float4 g_m4[NNODES * 32];          // message = h @ W^T (16B aligned)
__device__ float4 g_h4[NNODES * 32];          // activations (16B aligned)

// Output layout (floats): logits | probs | emb | distance
#define OFF_LOGIT 0
#define OFF_PROB  ((size_t)NNODES * NCLS)
#define OFF_EMB   ((size_t)NNODES * 2 * NCLS)
#define OFF_DIST  ((size_t)NNODES * (2 * NCLS + FDIM))

// ---------------- dtype detection ----------------
// int64 indices < 50000 have all-zero high words; int32 indices are random
// node ids, so 1024 consecutive odd words being zero has probability ~0.
__global__ void k_detect(const int* __restrict__ ei32) {
    if (threadIdx.x == 0 && blockIdx.x == 0) {
        int allzero = 1;
        for (int i = 0; i < 1024; i++)
            if (ei32[2 * i + 1] != 0) { allzero = 0; break; }
        g_is64 = allzero;
    }
}

__device__ __forceinline__ int edge_at(const void* ei, long long idx) {
    long long v = g_is64 ? ((const long long*)ei)[idx]
                         : (long long)((const int*)ei)[idx];
    int i = (int)v;
    i = (i < 0) ? 0 : i;
    return (i >= NNODES) ? (NNODES - 1) : i;   // clamp: never trap
}

// ---------------- degree / CSR build ----------------
__global__ void k_zero_ints(int* a, int n) {
    int i = blockIdx.x * blockDim.x + threadIdx.x;
    if (i < n) a[i] = 0;
}

__global__ void k_deg_count(const void* __restrict__ ei, long long E) {
    long long e = (long long)blockIdx.x * blockDim.x + threadIdx.x;
    if (e < E) atomicAdd(&g_degi[edge_at(ei, E + e)], 1);
}

__global__ void k_deg_finish() {
    int i = blockIdx.x * blockDim.x + threadIdx.x;
    if (i < NNODES) g_dinv[i] = rsqrtf((float)(g_degi[i] + 1));  // +1 self loop
}

// one-block exclusive scan of g_degi -> g_rowptr (1024 threads, 49 elems/thread)
__global__ void k_scan() {
    __shared__ int s[1024];
    const int C = 49;
    int t = threadIdx.x;
    int base = t * C;
    int sum = 0;
    for (int i = 0; i < C; i++) {
        int idx = base + i;
        if (idx < NNODES) sum += g_degi[idx];
    }
    s[t] = sum;
    __syncthreads();
    for (int o = 1; o < 1024; o <<= 1) {
        int v = (t >= o) ? s[t - o] : 0;
        __syncthreads();
        s[t] += v;
        __syncthreads();
    }
    int run = (t > 0) ? s[t - 1] : 0;
    for (int i = 0; i < C; i++) {
        int idx = base + i;
        if (idx < NNODES) { g_rowptr[idx] = run; run += g_degi[idx]; }
    }
    if (t == 1023) g_rowptr[NNODES] = s[1023];
}

__global__ void k_fill(const void* __restrict__ ei, long long E) {
    long long e = (long long)blockIdx.x * blockDim.x + threadIdx.x;
    if (e >= E) return;
    int src = edge_at(ei, e);
    int dst = edge_at(ei, E + e);
    int pos = g_rowptr[dst] + atomicAdd(&g_cursor[dst], 1);
    if (pos >= 0 && pos < EMAX) {
        g_csrsrc[pos] = src;
        g_csrw[pos] = g_dinv[src] * g_dinv[dst];
    }
}

// ---------------- GEMM: C[n,f] = sum_k A[n,k] * W[f,k]  (F = 128) --------
template<int K>
__global__ __launch_bounds__(256) void k_gemm_nt(const float* __restrict__ A,
                                                 const float* __restrict__ W,
                                                 float4* __restrict__ C4) {
    const int BM = 64, BK = 32;
    __shared__ float As[BM][BK + 4];
    __shared__ float Ws[FDIM][BK + 1];

    int tid = threadIdx.x;
    int tx = tid & 15;
    int ty = tid >> 4;
    int row0 = blockIdx.x * BM;

    float acc[4][8];
#pragma unroll
    for (int i = 0; i < 4; i++)
#pragma unroll
        for (int j = 0; j < 8; j++) acc[i][j] = 0.f;

    int lr = tid >> 3;
    int lk = tid & 7;

    for (int k0 = 0; k0 < K; k0 += BK) {
#pragma unroll
        for (int r = 0; r < 2; r++) {
            int row = lr + r * 32;
            float4 v = make_float4(0.f, 0.f, 0.f, 0.f);
            int grow = row0 + row;
            if (grow < NNODES)
                v = *(const float4*)&A[(size_t)grow * K + k0 + lk * 4];
            *(float4*)&As[row][lk * 4] = v;
        }
#pragma unroll
        for (int r = 0; r < 4; r++) {
            int f = lr + r * 32;
            float4 v = *(const float4*)&W[(size_t)f * K + k0 + lk * 4];
            Ws[f][lk * 4 + 0] = v.x;
            Ws[f][lk * 4 + 1] = v.y;
            Ws[f][lk * 4 + 2] = v.z;
            Ws[f][lk * 4 + 3] = v.w;
        }
        __syncthreads();

#pragma unroll
        for (int k = 0; k < BK; k++) {
            float a[4], b[8];
#pragma unroll
            for (int i = 0; i < 4; i++) a[i] = As[ty * 4 + i][k];
#pragma unroll
            for (int j = 0; j < 8; j++) b[j] = Ws[tx + 16 * j][k];
#pragma unroll
            for (int i = 0; i < 4; i++)
#pragma unroll
                for (int j = 0; j < 8; j++) acc[i][j] += a[i] * b[j];
        }
        __syncthreads();
    }

    float* C = (float*)C4;
#pragma unroll
    for (int i = 0; i < 4; i++) {
        int row = row0 + ty * 4 + i;
        if (row < NNODES) {
#pragma unroll
            for (int j = 0; j < 8; j++)
                C[(size_t)row * FDIM + tx + 16 * j] = acc[i][j];
        }
    }
}

// ---------------- gather: h = relu(sum_in w*m[src] + dinv^2*m[self] + b) --
__global__ __launch_bounds__(256) void k_gather(const float* __restrict__ b) {
    int warp = threadIdx.x >> 5, lane = threadIdx.x & 31;
    int node = blockIdx.x * 8 + warp;
    if (node >= NNODES) return;

    int s0 = g_rowptr[node];
    int s1 = g_rowptr[node + 1];
    float w0 = g_dinv[node];
    w0 = w0 * w0;

    float4 mm = g_m4[(size_t)node * 32 + lane];
    float4 bb = ((const float4*)b)[lane];
    float4 acc;
    acc.x = fmaf(w0, mm.x, bb.x);
    acc.y = fmaf(w0, mm.y, bb.y);
    acc.z = fmaf(w0, mm.z, bb.z);
    acc.w = fmaf(w0, mm.w, bb.w);

    for (int j = s0; j < s1; j++) {
        int s = g_csrsrc[j];
        float w = g_csrw[j];
        float4 v = g_m4[(size_t)s * 32 + lane];
        acc.x = fmaf(w, v.x, acc.x);
        acc.y = fmaf(w, v.y, acc.y);
        acc.z = fmaf(w, v.z, acc.z);
        acc.w = fmaf(w, v.w, acc.w);
    }
    acc.x = fmaxf(acc.x, 0.f);
    acc.y = fmaxf(acc.y, 0.f);
    acc.z = fmaxf(acc.z, 0.f);
    acc.w = fmaxf(acc.w, 0.f);
    g_h4[(size_t)node * 32 + lane] = acc;
}

// ---------------- prototype head: warp per node ----------------
__global__ __launch_bounds__(256) void k_proto(const float* __restrict__ protos,
                                               const float* __restrict__ last_w,
                                               float* __restrict__ out) {
    __shared__ float sp[NPROTO][132];
    __shared__ float slw[NCLS][52];
    __shared__ float se[8][132];
    __shared__ float ssim[8][52];
    __shared__ float slog[8][12];

    int tid = threadIdx.x;
    for (int i = tid; i < NPROTO * 32; i += 256) {
        int p = i >> 5, k = i & 31;
        ((float4*)&sp[p][0])[k] = ((const float4*)protos)[p * 32 + k];
    }
    for (int i = tid; i < NCLS * NPROTO; i += 256)
        slw[i / NPROTO][i % NPROTO] = last_w[i];
    __syncthreads();

    int warp = tid >> 5, lane = tid & 31;
    int node = blockIdx.x * 8 + warp;
    if (node >= NNODES) return;

    float4 ev = g_h4[(size_t)node * 32 + lane];
    ((float4*)&se[warp][0])[lane] = ev;
    float en = ev.x * ev.x + ev.y * ev.y + ev.z * ev.z + ev.w * ev.w;
#pragma unroll
    for (int o = 16; o > 0; o >>= 1) en += __shfl_xor_sync(0xFFFFFFFFu, en, o);
    __syncwarp();

#pragma unroll
    for (int pi = 0; pi < 2; pi++) {
        int p = lane + 32 * pi;
        if (p < NPROTO) {
            float dot = 0.f, pn = 0.f;
#pragma unroll 8
            for (int k = 0; k < 32; k++) {
                float4 e4 = ((float4*)&se[warp][0])[k];
                float4 p4 = ((float4*)&sp[p][0])[k];
                dot += e4.x * p4.x + e4.y * p4.y + e4.z * p4.z + e4.w * p4.w;
                pn  += p4.x * p4.x + p4.y * p4.y + p4.z * p4.z + p4.w * p4.w;
            }
            float d = en - 2.f * dot + pn;
            ssim[warp][p] = logf((d + 1.0f) / (d + EPSV));
            out[OFF_DIST + (size_t)node * NPROTO + p] = d;
        }
    }
    __syncwarp();

    float logit = 0.f;
    if (lane < NCLS) {
#pragma unroll 10
        for (int p = 0; p < NPROTO; p++) logit += ssim[warp][p] * slw[lane][p];
        slog[warp][lane] = logit;
        out[OFF_LOGIT + (size_t)node * NCLS + lane] = logit;
    }
    __syncwarp();
    if (lane < NCLS) {
        float mx = -1e30f;
#pragma unroll
        for (int c = 0; c < NCLS; c++) mx = fmaxf(mx, slog[warp][c]);
        float s = 0.f;
#pragma unroll
        for (int c = 0; c < NCLS; c++) s += expf(slog[warp][c] - mx);
        out[OFF_PROB + (size_t)node * NCLS + lane] = expf(logit - mx) / s;
    }
    ((float4*)(out + OFF_EMB))[(size_t)node * 32 + lane] = ev;
}

// ---------------- launch ----------------
extern "C" void kernel_launch(void* const* d_in, const int* in_sizes, int n_in,
                              void* d_out, int out_size) {
    const float* x   = (const float*)d_in[0];
    const void*  ei  = d_in[1];
    const float* W1  = (const float*)d_in[2];
    const float* b1  = (const float*)d_in[3];
    const float* W2  = (const float*)d_in[4];
    const float* b2  = (const float*)d_in[5];
    const float* W3  = (const float*)d_in[6];
    const float* b3  = (const float*)d_in[7];
    const float* pv  = (const float*)d_in[8];
    const float* lw  = (const float*)d_in[9];
    float* out = (float*)d_out;
    long long E = (long long)(in_sizes[1] / 2);

    float4 *m4, *h4;
    int *degi, *cursor;
    cudaGetSymbolAddress((void**)&m4,     g_m4);
    cudaGetSymbolAddress((void**)&h4,     g_h4);
    cudaGetSymbolAddress((void**)&degi,   g_degi);
    cudaGetSymbolAddress((void**)&cursor, g_cursor);

    const int T = 256;
    int nblkN  = (NNODES + T - 1) / T;
    int nblkE  = (int)((E + T - 1) / T);
    int nblkGm = (NNODES + 63) / 64;
    int nblkW  = (NNODES + 7) / 8;   // warp-per-node kernels

    // ---- dtype detect + CSR build (amortized over 3 layers) ----
    k_detect<<<1, 32>>>((const int*)ei);
    k_zero_ints<<<nblkN, T>>>(degi, NNODES);
    k_zero_ints<<<nblkN, T>>>(cursor, NNODES);
    k_deg_count<<<nblkE, T>>>(ei, E);
    k_deg_finish<<<nblkN, T>>>();
    k_scan<<<1, 1024>>>();
    k_fill<<<nblkE, T>>>(ei, E);

    // ---- layer 1 (K=512) ----
    k_gemm_nt<512><<<nblkGm, T>>>(x, W1, m4);
    k_gather<<<nblkW, T>>>(b1);

    // ---- layer 2 (K=128) ----
    k_gemm_nt<128><<<nblkGm, T>>>((const float*)h4, W2, m4);
    k_gather<<<nblkW, T>>>(b2);

    // ---- layer 3 (K=128) ----
    k_gemm_nt<128><<<nblkGm, T>>>((const float*)h4, W3, m4);
    k_gather<<<nblkW, T>>>(b3);

    // ---- prototype head + outputs ----
    k_proto<<<nblkW, T>>>(pv, lw, out);
}

// round 13
// speedup vs baseline: 1.1793x; 1.1793x over previous
#include <cuda_runtime.h>
#include <cuda_bf16.h>
#include <math.h>
#include <stdint.h>

#define NNODES 50000
#define FDIM   128
#define NPROTO 50
#define NCLS   10
#define EPSV   1e-4f
#define EMAX   640000

// ---------------- scratch (device globals; no allocation) ----------------
__device__ int    g_is64;                     // edge_index dtype flag
__device__ float  g_dinv[NNODES];             // deg^{-1/2}
__device__ int    g_degi[NNODES];             // edge-only in-degree
__device__ int    g_rowptr[NNODES + 1];
__device__ int    g_cursor[NNODES];
__device__ int    g_csrsrc[EMAX];
__device__ float  g_csrw[EMAX];
__device__ float4 g_m4[NNODES * 32];          // message = h @ W^T (16B aligned)
__device__ float4 g_h4[NNODES * 32];          // activations (16B aligned)

// Output layout (floats): logits | probs | emb | distance
#define OFF_LOGIT 0
#define OFF_PROB  ((size_t)NNODES * NCLS)
#define OFF_EMB   ((size_t)NNODES * 2 * NCLS)
#define OFF_DIST  ((size_t)NNODES * (2 * NCLS + FDIM))

// ---------------- dtype detection ----------------
__global__ void k_detect(const int* __restrict__ ei32) {
    if (threadIdx.x == 0 && blockIdx.x == 0) {
        int allzero = 1;
        for (int i = 0; i < 1024; i++)
            if (ei32[2 * i + 1] != 0) { allzero = 0; break; }
        g_is64 = allzero;
    }
}

__device__ __forceinline__ int edge_at(const void* ei, long long idx) {
    long long v = g_is64 ? ((const long long*)ei)[idx]
                         : (long long)((const int*)ei)[idx];
    int i = (int)v;
    i = (i < 0) ? 0 : i;
    return (i >= NNODES) ? (NNODES - 1) : i;   // clamp: never trap
}

// ---------------- degree / CSR build ----------------
__global__ void k_zero_ints(int* a, int n) {
    int i = blockIdx.x * blockDim.x + threadIdx.x;
    if (i < n) a[i] = 0;
}

__global__ void k_deg_count(const void* __restrict__ ei, long long E) {
    long long e = (long long)blockIdx.x * blockDim.x + threadIdx.x;
    if (e < E) atomicAdd(&g_degi[edge_at(ei, E + e)], 1);
}

__global__ void k_deg_finish() {
    int i = blockIdx.x * blockDim.x + threadIdx.x;
    if (i < NNODES) g_dinv[i] = rsqrtf((float)(g_degi[i] + 1));  // +1 self loop
}

__global__ void k_scan() {
    __shared__ int s[1024];
    const int C = 49;
    int t = threadIdx.x;
    int base = t * C;
    int sum = 0;
    for (int i = 0; i < C; i++) {
        int idx = base + i;
        if (idx < NNODES) sum += g_degi[idx];
    }
    s[t] = sum;
    __syncthreads();
    for (int o = 1; o < 1024; o <<= 1) {
        int v = (t >= o) ? s[t - o] : 0;
        __syncthreads();
        s[t] += v;
        __syncthreads();
    }
    int run = (t > 0) ? s[t - 1] : 0;
    for (int i = 0; i < C; i++) {
        int idx = base + i;
        if (idx < NNODES) { g_rowptr[idx] = run; run += g_degi[idx]; }
    }
    if (t == 1023) g_rowptr[NNODES] = s[1023];
}

__global__ void k_fill(const void* __restrict__ ei, long long E) {
    long long e = (long long)blockIdx.x * blockDim.x + threadIdx.x;
    if (e >= E) return;
    int src = edge_at(ei, e);
    int dst = edge_at(ei, E + e);
    int pos = g_rowptr[dst] + atomicAdd(&g_cursor[dst], 1);
    if (pos >= 0 && pos < EMAX) {
        g_csrsrc[pos] = src;
        g_csrw[pos] = g_dinv[src] * g_dinv[dst];
    }
}

// =============== tensor-core GEMM via mma.sync (tf32, 3x split) ==========
// C[n,f] = sum_k A[n,k] * W[f,k].  CTA tile: 128 rows x 128 cols, BK=32.
// 8 warps; warp w owns rows [16w, 16w+16), all 128 cols.
// Smem: Ahi|Alo|Bhi|Blo, each 128 x 36 floats (stride 36 -> f4-aligned,
// conflict-free fragment reads).

__device__ __forceinline__ uint32_t f2tf32(float a) {
    uint32_t u;
    asm("cvt.rna.tf32.f32 %0, %1;" : "=r"(u) : "f"(a));
    return u;
}

__device__ __forceinline__ void mma_tf32(float* c, const uint32_t* a, const uint32_t* b) {
    asm volatile(
        "mma.sync.aligned.m16n8k8.row.col.f32.tf32.tf32.f32 "
        "{%0,%1,%2,%3}, {%4,%5,%6,%7}, {%8,%9}, {%0,%1,%2,%3};"
        : "+f"(c[0]), "+f"(c[1]), "+f"(c[2]), "+f"(c[3])
        : "r"(a[0]), "r"(a[1]), "r"(a[2]), "r"(a[3]), "r"(b[0]), "r"(b[1]));
}

#define SSTR 36
#define SM_MMA_BYTES (4 * 128 * SSTR * 4)

template<int K>
__global__ __launch_bounds__(256, 1) void k_gemm_mma(const float* __restrict__ A,
                                                     const float* __restrict__ W,
                                                     float* __restrict__ C) {
    extern __shared__ float sm[];
    float* sAh = sm;
    float* sAl = sm + 128 * SSTR;
    float* sBh = sm + 2 * 128 * SSTR;
    float* sBl = sm + 3 * 128 * SSTR;

    int tid = threadIdx.x;
    int w = tid >> 5, lane = tid & 31;
    int g = lane >> 2, tig = lane & 3;       // mma groupID / thread-in-group
    int row0 = blockIdx.x * 128;

    float acc[16][4];
#pragma unroll
    for (int j = 0; j < 16; j++)
#pragma unroll
        for (int q = 0; q < 4; q++) acc[j][q] = 0.f;

    for (int kb = 0; kb < K / 32; kb++) {
        int k0 = kb * 32;
        // fill smem: 1024 float4 per matrix, 4 per thread
#pragma unroll
        for (int t = 0; t < 4; t++) {
            int idx = tid + t * 256;
            int row = idx >> 3;              // 0..127
            int c4  = idx & 7;               // float4 slot in 32-float row
            // A (guarded)
            float4 av = make_float4(0.f, 0.f, 0.f, 0.f);
            int rg = row0 + row;
            if (rg < NNODES) av = *(const float4*)&A[(size_t)rg * K + k0 + c4 * 4];
            float4 ah, al;
            ah.x = __uint_as_float(f2tf32(av.x)); al.x = __uint_as_float(f2tf32(av.x - ah.x));
            ah.y = __uint_as_float(f2tf32(av.y)); al.y = __uint_as_float(f2tf32(av.y - ah.y));
            ah.z = __uint_as_float(f2tf32(av.z)); al.z = __uint_as_float(f2tf32(av.z - ah.z));
            ah.w = __uint_as_float(f2tf32(av.w)); al.w = __uint_as_float(f2tf32(av.w - ah.w));
            *(float4*)&sAh[row * SSTR + c4 * 4] = ah;
            *(float4*)&sAl[row * SSTR + c4 * 4] = al;
            // B = W rows (always 128 valid rows)
            float4 bv = *(const float4*)&W[(size_t)row * K + k0 + c4 * 4];
            float4 bh, bl;
            bh.x = __uint_as_float(f2tf32(bv.x)); bl.x = __uint_as_float(f2tf32(bv.x - bh.x));
            bh.y = __uint_as_float(f2tf32(bv.y)); bl.y = __uint_as_float(f2tf32(bv.y - bh.y));
            bh.z = __uint_as_float(f2tf32(bv.z)); bl.z = __uint_as_float(f2tf32(bv.z - bh.z));
            bh.w = __uint_as_float(f2tf32(bv.w)); bl.w = __uint_as_float(f2tf32(bv.w - bh.w));
            *(float4*)&sBh[row * SSTR + c4 * 4] = bh;
            *(float4*)&sBl[row * SSTR + c4 * 4] = bl;
        }
        __syncthreads();

#pragma unroll
        for (int ks = 0; ks < 4; ks++) {
            int kk = ks * 8;
            int ar0 = (w * 16 + g) * SSTR + kk + tig;       // row g
            int ar1 = (w * 16 + g + 8) * SSTR + kk + tig;   // row g+8
            uint32_t ah[4], al[4];
            ah[0] = __float_as_uint(sAh[ar0]);
            ah[1] = __float_as_uint(sAh[ar1]);
            ah[2] = __float_as_uint(sAh[ar0 + 4]);
            ah[3] = __float_as_uint(sAh[ar1 + 4]);
            al[0] = __float_as_uint(sAl[ar0]);
            al[1] = __float_as_uint(sAl[ar1]);
            al[2] = __float_as_uint(sAl[ar0 + 4]);
            al[3] = __float_as_uint(sAl[ar1 + 4]);
#pragma unroll
            for (int j = 0; j < 16; j++) {
                int br = (j * 8 + g) * SSTR + kk + tig;
                uint32_t bh[2], bl[2];
                bh[0] = __float_as_uint(sBh[br]);
                bh[1] = __float_as_uint(sBh[br + 4]);
                bl[0] = __float_as_uint(sBl[br]);
                bl[1] = __float_as_uint(sBl[br + 4]);
                mma_tf32(acc[j], ah, bh);
                mma_tf32(acc[j], ah, bl);
                mma_tf32(acc[j], al, bh);
            }
        }
        __syncthreads();
    }

    // epilogue: float2 stores
    int r1 = row0 + w * 16 + g;
    int r2 = r1 + 8;
#pragma unroll
    for (int j = 0; j < 16; j++) {
        int col = j * 8 + tig * 2;
        if (r1 < NNODES)
            *(float2*)&C[(size_t)r1 * FDIM + col] = make_float2(acc[j][0], acc[j][1]);
        if (r2 < NNODES)
            *(float2*)&C[(size_t)r2 * FDIM + col] = make_float2(acc[j][2], acc[j][3]);
    }
}

// ---------------- gather: h = relu(sum_in w*m[src] + dinv^2*m[self] + b) --
__global__ __launch_bounds__(256) void k_gather(const float* __restrict__ b) {
    int warp = threadIdx.x >> 5, lane = threadIdx.x & 31;
    int node = blockIdx.x * 8 + warp;
    if (node >= NNODES) return;

    int s0 = g_rowptr[node];
    int s1 = g_rowptr[node + 1];
    float w0 = g_dinv[node];
    w0 = w0 * w0;

    float4 mm = g_m4[(size_t)node * 32 + lane];
    float4 bb = ((const float4*)b)[lane];
    float4 acc;
    acc.x = fmaf(w0, mm.x, bb.x);
    acc.y = fmaf(w0, mm.y, bb.y);
    acc.z = fmaf(w0, mm.z, bb.z);
    acc.w = fmaf(w0, mm.w, bb.w);

    for (int j = s0; j < s1; j++) {
        int s = g_csrsrc[j];
        float w = g_csrw[j];
        float4 v = g_m4[(size_t)s * 32 + lane];
        acc.x = fmaf(w, v.x, acc.x);
        acc.y = fmaf(w, v.y, acc.y);
        acc.z = fmaf(w, v.z, acc.z);
        acc.w = fmaf(w, v.w, acc.w);
    }
    acc.x = fmaxf(acc.x, 0.f);
    acc.y = fmaxf(acc.y, 0.f);
    acc.z = fmaxf(acc.z, 0.f);
    acc.w = fmaxf(acc.w, 0.f);
    g_h4[(size_t)node * 32 + lane] = acc;
}

// ---------------- prototype head: warp per node ----------------
__global__ __launch_bounds__(256) void k_proto(const float* __restrict__ protos,
                                               const float* __restrict__ last_w,
                                               float* __restrict__ out) {
    __shared__ float sp[NPROTO][132];
    __shared__ float slw[NCLS][52];
    __shared__ float se[8][132];
    __shared__ float ssim[8][52];
    __shared__ float slog[8][12];

    int tid = threadIdx.x;
    for (int i = tid; i < NPROTO * 32; i += 256) {
        int p = i >> 5, k = i & 31;
        ((float4*)&sp[p][0])[k] = ((const float4*)protos)[p * 32 + k];
    }
    for (int i = tid; i < NCLS * NPROTO; i += 256)
        slw[i / NPROTO][i % NPROTO] = last_w[i];
    __syncthreads();

    int warp = tid >> 5, lane = tid & 31;
    int node = blockIdx.x * 8 + warp;
    if (node >= NNODES) return;

    float4 ev = g_h4[(size_t)node * 32 + lane];
    ((float4*)&se[warp][0])[lane] = ev;
    float en = ev.x * ev.x + ev.y * ev.y + ev.z * ev.z + ev.w * ev.w;
#pragma unroll
    for (int o = 16; o > 0; o >>= 1) en += __shfl_xor_sync(0xFFFFFFFFu, en, o);
    __syncwarp();

#pragma unroll
    for (int pi = 0; pi < 2; pi++) {
        int p = lane + 32 * pi;
        if (p < NPROTO) {
            float dot = 0.f, pn = 0.f;
#pragma unroll 8
            for (int k = 0; k < 32; k++) {
                float4 e4 = ((float4*)&se[warp][0])[k];
                float4 p4 = ((float4*)&sp[p][0])[k];
                dot += e4.x * p4.x + e4.y * p4.y + e4.z * p4.z + e4.w * p4.w;
                pn  += p4.x * p4.x + p4.y * p4.y + p4.z * p4.z + p4.w * p4.w;
            }
            float d = en - 2.f * dot + pn;
            ssim[warp][p] = logf((d + 1.0f) / (d + EPSV));
            out[OFF_DIST + (size_t)node * NPROTO + p] = d;
        }
    }
    __syncwarp();

    float logit = 0.f;
    if (lane < NCLS) {
#pragma unroll 10
        for (int p = 0; p < NPROTO; p++) logit += ssim[warp][p] * slw[lane][p];
        slog[warp][lane] = logit;
        out[OFF_LOGIT + (size_t)node * NCLS + lane] = logit;
    }
    __syncwarp();
    if (lane < NCLS) {
        float mx = -1e30f;
#pragma unroll
        for (int c = 0; c < NCLS; c++) mx = fmaxf(mx, slog[warp][c]);
        float s = 0.f;
#pragma unroll
        for (int c = 0; c < NCLS; c++) s += expf(slog[warp][c] - mx);
        out[OFF_PROB + (size_t)node * NCLS + lane] = expf(logit - mx) / s;
    }
    ((float4*)(out + OFF_EMB))[(size_t)node * 32 + lane] = ev;
}

// ---------------- launch ----------------
extern "C" void kernel_launch(void* const* d_in, const int* in_sizes, int n_in,
                              void* d_out, int out_size) {
    const float* x   = (const float*)d_in[0];
    const void*  ei  = d_in[1];
    const float* W1  = (const float*)d_in[2];
    const float* b1  = (const float*)d_in[3];
    const float* W2  = (const float*)d_in[4];
    const float* b2  = (const float*)d_in[5];
    const float* W3  = (const float*)d_in[6];
    const float* b3  = (const float*)d_in[7];
    const float* pv  = (const float*)d_in[8];
    const float* lw  = (const float*)d_in[9];
    float* out = (float*)d_out;
    long long E = (long long)(in_sizes[1] / 2);

    float4 *m4, *h4;
    int *degi, *cursor;
    cudaGetSymbolAddress((void**)&m4,     g_m4);
    cudaGetSymbolAddress((void**)&h4,     g_h4);
    cudaGetSymbolAddress((void**)&degi,   g_degi);
    cudaGetSymbolAddress((void**)&cursor, g_cursor);

    cudaFuncSetAttribute(k_gemm_mma<512>, cudaFuncAttributeMaxDynamicSharedMemorySize, SM_MMA_BYTES);
    cudaFuncSetAttribute(k_gemm_mma<128>, cudaFuncAttributeMaxDynamicSharedMemorySize, SM_MMA_BYTES);

    const int T = 256;
    int nblkN  = (NNODES + T - 1) / T;
    int nblkE  = (int)((E + T - 1) / T);
    int nblkTc = (NNODES + 127) / 128;   // 391 GEMM tiles
    int nblkW  = (NNODES + 7) / 8;       // warp-per-node kernels

    // ---- dtype detect + CSR build (amortized over 3 layers) ----
    k_detect<<<1, 32>>>((const int*)ei);
    k_zero_ints<<<nblkN, T>>>(degi, NNODES);
    k_zero_ints<<<nblkN, T>>>(cursor, NNODES);
    k_deg_count<<<nblkE, T>>>(ei, E);
    k_deg_finish<<<nblkN, T>>>();
    k_scan<<<1, 1024>>>();
    k_fill<<<nblkE, T>>>(ei, E);

    // ---- layer 1 (K=512) ----
    k_gemm_mma<512><<<nblkTc, T, SM_MMA_BYTES>>>(x, W1, (float*)m4);
    k_gather<<<nblkW, T>>>(b1);

    // ---- layer 2 (K=128) ----
    k_gemm_mma<128><<<nblkTc, T, SM_MMA_BYTES>>>((const float*)h4, W2, (float*)m4);
    k_gather<<<nblkW, T>>>(b2);

    // ---- layer 3 (K=128) ----
    k_gemm_mma<128><<<nblkTc, T, SM_MMA_BYTES>>>((const float*)h4, W3, (float*)m4);
    k_gather<<<nblkW, T>>>(b3);

    // ---- prototype head + outputs ----
    k_proto<<<nblkW, T>>>(pv, lw, out);
}

// round 16
// speedup vs baseline: 1.2651x; 1.0728x over previous
#include <cuda_runtime.h>
#include <cuda_bf16.h>
#include <math.h>
#include <stdint.h>

#define NNODES 50000
#define FDIM   128
#define NPROTO 50
#define NCLS   10
#define EPSV   1e-4f
#define EMAX   640000

// ---------------- scratch (device globals; no allocation) ----------------
__device__ int    g_is64;                     // edge_index dtype flag
__device__ float  g_dinv[NNODES];             // deg^{-1/2}
__device__ int    g_degi[NNODES];             // edge-only in-degree
__device__ int    g_rowptr[NNODES + 1];
__device__ int    g_cursor[NNODES];
__device__ int    g_csrsrc[EMAX];
__device__ float  g_csrw[EMAX];
__device__ float4 g_m4[NNODES * 32];          // message = h @ W^T (16B aligned)
__device__ float4 g_h4[NNODES * 32];          // activations (16B aligned)

// Output layout (floats): logits | probs | emb | distance
#define OFF_LOGIT 0
#define OFF_PROB  ((size_t)NNODES * NCLS)
#define OFF_EMB   ((size_t)NNODES * 2 * NCLS)
#define OFF_DIST  ((size_t)NNODES * (2 * NCLS + FDIM))

// ---------------- dtype detection ----------------
__global__ void k_detect(const int* __restrict__ ei32) {
    if (threadIdx.x == 0 && blockIdx.x == 0) {
        int allzero = 1;
        for (int i = 0; i < 1024; i++)
            if (ei32[2 * i + 1] != 0) { allzero = 0; break; }
        g_is64 = allzero;
    }
}

__device__ __forceinline__ int edge_at(const void* ei, long long idx) {
    long long v = g_is64 ? ((const long long*)ei)[idx]
                         : (long long)((const int*)ei)[idx];
    int i = (int)v;
    i = (i < 0) ? 0 : i;
    return (i >= NNODES) ? (NNODES - 1) : i;   // clamp: never trap
}

// ---------------- degree / CSR build ----------------
__global__ void k_zero_ints(int* a, int n) {
    int i = blockIdx.x * blockDim.x + threadIdx.x;
    if (i < n) a[i] = 0;
}

__global__ void k_deg_count(const void* __restrict__ ei, long long E) {
    long long e = (long long)blockIdx.x * blockDim.x + threadIdx.x;
    if (e < E) atomicAdd(&g_degi[edge_at(ei, E + e)], 1);
}

__global__ void k_deg_finish() {
    int i = blockIdx.x * blockDim.x + threadIdx.x;
    if (i < NNODES) g_dinv[i] = rsqrtf((float)(g_degi[i] + 1));  // +1 self loop
}

__global__ void k_scan() {
    __shared__ int s[1024];
    const int C = 49;
    int t = threadIdx.x;
    int base = t * C;
    int sum = 0;
    for (int i = 0; i < C; i++) {
        int idx = base + i;
        if (idx < NNODES) sum += g_degi[idx];
    }
    s[t] = sum;
    __syncthreads();
    for (int o = 1; o < 1024; o <<= 1) {
        int v = (t >= o) ? s[t - o] : 0;
        __syncthreads();
        s[t] += v;
        __syncthreads();
    }
    int run = (t > 0) ? s[t - 1] : 0;
    for (int i = 0; i < C; i++) {
        int idx = base + i;
        if (idx < NNODES) { g_rowptr[idx] = run; run += g_degi[idx]; }
    }
    if (t == 1023) g_rowptr[NNODES] = s[1023];
}

__global__ void k_fill(const void* __restrict__ ei, long long E) {
    long long e = (long long)blockIdx.x * blockDim.x + threadIdx.x;
    if (e >= E) return;
    int src = edge_at(ei, e);
    int dst = edge_at(ei, E + e);
    int pos = g_rowptr[dst] + atomicAdd(&g_cursor[dst], 1);
    if (pos >= 0 && pos < EMAX) {
        g_csrsrc[pos] = src;
        g_csrw[pos] = g_dinv[src] * g_dinv[dst];
    }
}

// =============== tensor-core GEMM via mma.sync (tf32, 3x split) ==========
// C[n,f] = sum_k A[n,k] * W[f,k].  CTA tile: 128 rows x 128 cols, BK=32.
// 8 warps as 4x2: warp (wr, wc) owns rows [32*wr, 32*wr+32), cols [64*wc, +64).
// Register-prefetch pipeline hides LDG latency behind the MMA phase.
// Smem: Ahi|Alo|Bhi|Blo, each 128 x 36 floats (f4-aligned, conflict-free).

__device__ __forceinline__ uint32_t f2tf32(float a) {
    uint32_t u;
    asm("cvt.rna.tf32.f32 %0, %1;" : "=r"(u) : "f"(a));
    return u;
}

__device__ __forceinline__ void mma_tf32(float* c, const uint32_t* a, const uint32_t* b) {
    asm volatile(
        "mma.sync.aligned.m16n8k8.row.col.f32.tf32.tf32.f32 "
        "{%0,%1,%2,%3}, {%4,%5,%6,%7}, {%8,%9}, {%0,%1,%2,%3};"
        : "+f"(c[0]), "+f"(c[1]), "+f"(c[2]), "+f"(c[3])
        : "r"(a[0]), "r"(a[1]), "r"(a[2]), "r"(a[3]), "r"(b[0]), "r"(b[1]));
}

__device__ __forceinline__ void split4(float4 v, float4& hi, float4& lo) {
    hi.x = __uint_as_float(f2tf32(v.x)); lo.x = __uint_as_float(f2tf32(v.x - hi.x));
    hi.y = __uint_as_float(f2tf32(v.y)); lo.y = __uint_as_float(f2tf32(v.y - hi.y));
    hi.z = __uint_as_float(f2tf32(v.z)); lo.z = __uint_as_float(f2tf32(v.z - hi.z));
    hi.w = __uint_as_float(f2tf32(v.w)); lo.w = __uint_as_float(f2tf32(v.w - hi.w));
}

#define SSTR 36
#define SM_MMA_BYTES (4 * 128 * SSTR * 4)

template<int K>
__global__ __launch_bounds__(256, 1) void k_gemm_mma(const float* __restrict__ A,
                                                     const float* __restrict__ W,
                                                     float* __restrict__ C) {
    extern __shared__ float sm[];
    float* sAh = sm;
    float* sAl = sm + 128 * SSTR;
    float* sBh = sm + 2 * 128 * SSTR;
    float* sBl = sm + 3 * 128 * SSTR;

    int tid = threadIdx.x;
    int w = tid >> 5, lane = tid & 31;
    int g = lane >> 2, tig = lane & 3;       // mma groupID / thread-in-group
    int wr = w & 3, wc = w >> 2;             // 4x2 warp grid
    int row0 = blockIdx.x * 128;

    // fill mapping: thread covers 4 (row, c4) slots
    const int frow = tid >> 3;               // base row 0..31 pattern via idx
    (void)frow;

    float acc[2][8][4];
#pragma unroll
    for (int tm = 0; tm < 2; tm++)
#pragma unroll
        for (int j = 0; j < 8; j++)
#pragma unroll
            for (int q = 0; q < 4; q++) acc[tm][j][q] = 0.f;

    const int nkb = K / 32;

    // ---- prefetch tile 0 into registers ----
    float4 pA[4], pB[4];
#pragma unroll
    for (int t = 0; t < 4; t++) {
        int idx = tid + t * 256;
        int row = idx >> 3, c4 = idx & 7;
        int rg = row0 + row;
        pA[t] = make_float4(0.f, 0.f, 0.f, 0.f);
        if (rg < NNODES) pA[t] = *(const float4*)&A[(size_t)rg * K + c4 * 4];
        pB[t] = *(const float4*)&W[(size_t)row * K + c4 * 4];
    }

    for (int kb = 0; kb < nkb; kb++) {
        // ---- convert + store current tile to smem ----
#pragma unroll
        for (int t = 0; t < 4; t++) {
            int idx = tid + t * 256;
            int row = idx >> 3, c4 = idx & 7;
            float4 hi, lo;
            split4(pA[t], hi, lo);
            *(float4*)&sAh[row * SSTR + c4 * 4] = hi;
            *(float4*)&sAl[row * SSTR + c4 * 4] = lo;
            split4(pB[t], hi, lo);
            *(float4*)&sBh[row * SSTR + c4 * 4] = hi;
            *(float4*)&sBl[row * SSTR + c4 * 4] = lo;
        }
        __syncthreads();

        // ---- prefetch next tile (overlaps with MMA phase) ----
        if (kb + 1 < nkb) {
            int k0 = (kb + 1) * 32;
#pragma unroll
            for (int t = 0; t < 4; t++) {
                int idx = tid + t * 256;
                int row = idx >> 3, c4 = idx & 7;
                int rg = row0 + row;
                pA[t] = make_float4(0.f, 0.f, 0.f, 0.f);
                if (rg < NNODES) pA[t] = *(const float4*)&A[(size_t)rg * K + k0 + c4 * 4];
                pB[t] = *(const float4*)&W[(size_t)row * K + k0 + c4 * 4];
            }
        }

        // ---- MMA phase over 4 x 8-K steps ----
#pragma unroll
        for (int ks = 0; ks < 4; ks++) {
            int kk = ks * 8;
            uint32_t ah[2][4], al[2][4];
#pragma unroll
            for (int tm = 0; tm < 2; tm++) {
                int ar0 = (wr * 32 + tm * 16 + g) * SSTR + kk + tig;
                int ar1 = ar0 + 8 * SSTR;
                ah[tm][0] = __float_as_uint(sAh[ar0]);
                ah[tm][1] = __float_as_uint(sAh[ar1]);
                ah[tm][2] = __float_as_uint(sAh[ar0 + 4]);
                ah[tm][3] = __float_as_uint(sAh[ar1 + 4]);
                al[tm][0] = __float_as_uint(sAl[ar0]);
                al[tm][1] = __float_as_uint(sAl[ar1]);
                al[tm][2] = __float_as_uint(sAl[ar0 + 4]);
                al[tm][3] = __float_as_uint(sAl[ar1 + 4]);
            }
            uint32_t bh[8][2], bl[8][2];
#pragma unroll
            for (int j = 0; j < 8; j++) {
                int br = (wc * 64 + j * 8 + g) * SSTR + kk + tig;
                bh[j][0] = __float_as_uint(sBh[br]);
                bh[j][1] = __float_as_uint(sBh[br + 4]);
                bl[j][0] = __float_as_uint(sBl[br]);
                bl[j][1] = __float_as_uint(sBl[br + 4]);
            }
#pragma unroll
            for (int tm = 0; tm < 2; tm++)
#pragma unroll
                for (int j = 0; j < 8; j++) {
                    mma_tf32(acc[tm][j], ah[tm], bh[j]);
                    mma_tf32(acc[tm][j], ah[tm], bl[j]);
                    mma_tf32(acc[tm][j], al[tm], bh[j]);
                }
        }
        __syncthreads();
    }

    // ---- epilogue: float2 stores ----
#pragma unroll
    for (int tm = 0; tm < 2; tm++) {
        int r1 = row0 + wr * 32 + tm * 16 + g;
        int r2 = r1 + 8;
#pragma unroll
        for (int j = 0; j < 8; j++) {
            int col = wc * 64 + j * 8 + tig * 2;
            if (r1 < NNODES)
                *(float2*)&C[(size_t)r1 * FDIM + col] = make_float2(acc[tm][j][0], acc[tm][j][1]);
            if (r2 < NNODES)
                *(float2*)&C[(size_t)r2 * FDIM + col] = make_float2(acc[tm][j][2], acc[tm][j][3]);
        }
    }
}

// ---------------- gather: h = relu(sum_in w*m[src] + dinv^2*m[self] + b) --
__global__ __launch_bounds__(256) void k_gather(const float* __restrict__ b) {
    int warp = threadIdx.x >> 5, lane = threadIdx.x & 31;
    int node = blockIdx.x * 8 + warp;
    if (node >= NNODES) return;

    int s0 = g_rowptr[node];
    int s1 = g_rowptr[node + 1];
    float w0 = g_dinv[node];
    w0 = w0 * w0;

    float4 mm = g_m4[(size_t)node * 32 + lane];
    float4 bb = ((const float4*)b)[lane];
    float4 acc;
    acc.x = fmaf(w0, mm.x, bb.x);
    acc.y = fmaf(w0, mm.y, bb.y);
    acc.z = fmaf(w0, mm.z, bb.z);
    acc.w = fmaf(w0, mm.w, bb.w);

    for (int j = s0; j < s1; j++) {
        int s = g_csrsrc[j];
        float w = g_csrw[j];
        float4 v = g_m4[(size_t)s * 32 + lane];
        acc.x = fmaf(w, v.x, acc.x);
        acc.y = fmaf(w, v.y, acc.y);
        acc.z = fmaf(w, v.z, acc.z);
        acc.w = fmaf(w, v.w, acc.w);
    }
    acc.x = fmaxf(acc.x, 0.f);
    acc.y = fmaxf(acc.y, 0.f);
    acc.z = fmaxf(acc.z, 0.f);
    acc.w = fmaxf(acc.w, 0.f);
    g_h4[(size_t)node * 32 + lane] = acc;
}

// ---------------- prototype head: warp per node ----------------
__global__ __launch_bounds__(256) void k_proto(const float* __restrict__ protos,
                                               const float* __restrict__ last_w,
                                               float* __restrict__ out) {
    __shared__ float sp[NPROTO][132];
    __shared__ float slw[NCLS][52];
    __shared__ float se[8][132];
    __shared__ float ssim[8][52];
    __shared__ float slog[8][12];

    int tid = threadIdx.x;
    for (int i = tid; i < NPROTO * 32; i += 256) {
        int p = i >> 5, k = i & 31;
        ((float4*)&sp[p][0])[k] = ((const float4*)protos)[p * 32 + k];
    }
    for (int i = tid; i < NCLS * NPROTO; i += 256)
        slw[i / NPROTO][i % NPROTO] = last_w[i];
    __syncthreads();

    int warp = tid >> 5, lane = tid & 31;
    int node = blockIdx.x * 8 + warp;
    if (node >= NNODES) return;

    float4 ev = g_h4[(size_t)node * 32 + lane];
    ((float4*)&se[warp][0])[lane] = ev;
    float en = ev.x * ev.x + ev.y * ev.y + ev.z * ev.z + ev.w * ev.w;
#pragma unroll
    for (int o = 16; o > 0; o >>= 1) en += __shfl_xor_sync(0xFFFFFFFFu, en, o);
    __syncwarp();

#pragma unroll
    for (int pi = 0; pi < 2; pi++) {
        int p = lane + 32 * pi;
        if (p < NPROTO) {
            float dot = 0.f, pn = 0.f;
#pragma unroll 8
            for (int k = 0; k < 32; k++) {
                float4 e4 = ((float4*)&se[warp][0])[k];
                float4 p4 = ((float4*)&sp[p][0])[k];
                dot += e4.x * p4.x + e4.y * p4.y + e4.z * p4.z + e4.w * p4.w;
                pn  += p4.x * p4.x + p4.y * p4.y + p4.z * p4.z + p4.w * p4.w;
            }
            float d = en - 2.f * dot + pn;
            ssim[warp][p] = logf((d + 1.0f) / (d + EPSV));
            out[OFF_DIST + (size_t)node * NPROTO + p] = d;
        }
    }
    __syncwarp();

    float logit = 0.f;
    if (lane < NCLS) {
#pragma unroll 10
        for (int p = 0; p < NPROTO; p++) logit += ssim[warp][p] * slw[lane][p];
        slog[warp][lane] = logit;
        out[OFF_LOGIT + (size_t)node * NCLS + lane] = logit;
    }
    __syncwarp();
    if (lane < NCLS) {
        float mx = -1e30f;
#pragma unroll
        for (int c = 0; c < NCLS; c++) mx = fmaxf(mx, slog[warp][c]);
        float s = 0.f;
#pragma unroll
        for (int c = 0; c < NCLS; c++) s += expf(slog[warp][c] - mx);
        out[OFF_PROB + (size_t)node * NCLS + lane] = expf(logit - mx) / s;
    }
    ((float4*)(out + OFF_EMB))[(size_t)node * 32 + lane] = ev;
}

// ---------------- launch ----------------
extern "C" void kernel_launch(void* const* d_in, const int* in_sizes, int n_in,
                              void* d_out, int out_size) {
    const float* x   = (const float*)d_in[0];
    const void*  ei  = d_in[1];
    const float* W1  = (const float*)d_in[2];
    const float* b1  = (const float*)d_in[3];
    const float* W2  = (const float*)d_in[4];
    const float* b2  = (const float*)d_in[5];
    const float* W3  = (const float*)d_in[6];
    const float* b3  = (const float*)d_in[7];
    const float* pv  = (const float*)d_in[8];
    const float* lw  = (const float*)d_in[9];
    float* out = (float*)d_out;
    long long E = (long long)(in_sizes[1] / 2);

    float4 *m4, *h4;
    int *degi, *cursor;
    cudaGetSymbolAddress((void**)&m4,     g_m4);
    cudaGetSymbolAddress((void**)&h4,     g_h4);
    cudaGetSymbolAddress((void**)&degi,   g_degi);
    cudaGetSymbolAddress((void**)&cursor, g_cursor);

    cudaFuncSetAttribute(k_gemm_mma<512>, cudaFuncAttributeMaxDynamicSharedMemorySize, SM_MMA_BYTES);
    cudaFuncSetAttribute(k_gemm_mma<128>, cudaFuncAttributeMaxDynamicSharedMemorySize, SM_MMA_BYTES);

    const int T = 256;
    int nblkN  = (NNODES + T - 1) / T;
    int nblkE  = (int)((E + T - 1) / T);
    int nblkTc = (NNODES + 127) / 128;   // 391 GEMM tiles
    int nblkW  = (NNODES + 7) / 8;       // warp-per-node kernels

    // ---- dtype detect + CSR build (amortized over 3 layers) ----
    k_detect<<<1, 32>>>((const int*)ei);
    k_zero_ints<<<nblkN, T>>>(degi, NNODES);
    k_zero_ints<<<nblkN, T>>>(cursor, NNODES);
    k_deg_count<<<nblkE, T>>>(ei, E);
    k_deg_finish<<<nblkN, T>>>();
    k_scan<<<1, 1024>>>();
    k_fill<<<nblkE, T>>>(ei, E);

    // ---- layer 1 (K=512) ----
    k_gemm_mma<512><<<nblkTc, T, SM_MMA_BYTES>>>(x, W1, (float*)m4);
    k_gather<<<nblkW, T>>>(b1);

    // ---- layer 2 (K=128) ----
    k_gemm_mma<128><<<nblkTc, T, SM_MMA_BYTES>>>((const float*)h4, W2, (float*)m4);
    k_gather<<<nblkW, T>>>(b2);

    // ---- layer 3 (K=128) ----
    k_gemm_mma<128><<<nblkTc, T, SM_MMA_BYTES>>>((const float*)h4, W3, (float*)m4);
    k_gather<<<nblkW, T>>>(b3);

    // ---- prototype head + outputs ----
    k_proto<<<nblkW, T>>>(pv, lw, out);
}